// round 11
// baseline (speedup 1.0000x reference)
#include <cuda_runtime.h>
#include <cuda_fp16.h>
#include <math.h>

#define NMAX 150016
#define EMAX 3200064

// ---------------- static device scratch ----------------
__device__ float  g_dinv[NMAX];
__device__ unsigned long long g_cd[NMAX];   // count<<40 | sum(w * 2^24)
__device__ int    g_cnt2[NMAX];
__device__ int    g_rs[NMAX + 2];
__device__ int    g_bsum[1024];
__device__ int    g_bsumP[1024];
__device__ int    g_bar;
__device__ __align__(16) int2 g_csr[EMAX];  // {src, dinv[src]*ew bits}
__device__ uint2  g_hh [NMAX * 16];         // fp16 features ping
__device__ uint2  g_hh2[NMAX * 16];         // fp16 features pong

__device__ __forceinline__ void fma4(float4& a, float s, const float4& w) {
    a.x += s * w.x; a.y += s * w.y; a.z += s * w.z; a.w += s * w.w;
}
__device__ __forceinline__ uint2 pack4h(const float4& v) {
    __half2 lo = __float22half2_rn(make_float2(v.x, v.y));
    __half2 hi = __float22half2_rn(make_float2(v.z, v.w));
    uint2 r;
    r.x = *(const unsigned*)&lo;
    r.y = *(const unsigned*)&hi;
    return r;
}
__device__ __forceinline__ float4 unpack4h(const uint2& pv) {
    float2 f0 = __half22float2(*(const __half2*)&pv.x);
    float2 f1 = __half22float2(*(const __half2*)&pv.y);
    return make_float4(f0.x, f0.y, f1.x, f1.y);
}
__device__ __forceinline__ void acc_h(float4& acc, float ww, const uint2& pv) {
    float2 f0 = __half22float2(*(const __half2*)&pv.x);
    float2 f1 = __half22float2(*(const __half2*)&pv.y);
    acc.x += ww * f0.x; acc.y += ww * f0.y;
    acc.z += ww * f1.x; acc.w += ww * f1.y;
}

// ---------------- launch 0: concat x=[U;I] (fp16) + zero counters ----------------
__global__ void k_concat(const float4* __restrict__ U, const float4* __restrict__ I,
                         int nu16, int tot16, int N) {
    int i = blockIdx.x * blockDim.x + threadIdx.x;
    if (i < tot16) {
        float4 v = (i < nu16) ? U[i] : I[i - nu16];
        g_hh[i] = pack4h(v);
    }
    if (i < N) { g_cd[i] = 0ULL; g_cnt2[i] = 0; }
    if (i == 0) g_bar = 0;
}

// ---------------- software grid barrier (single-wave persistent kernel) -------
__device__ __forceinline__ void gsync(int target) {
    __syncthreads();
    __threadfence();
    if (threadIdx.x == 0) {
        atomicAdd(&g_bar, 1);
        while (atomicAdd(&g_bar, 0) < target) { }
        __threadfence();
    }
    __syncthreads();
}

// ---- launch 1: fused count (packed 64-bit atomic) + scan + dinv + block offsets ----
__global__ __launch_bounds__(1024) void k_cntscan(const int* __restrict__ dst,
                                                  const float* __restrict__ ew,
                                                  int E, int N, int nb) {
    __shared__ int sm[1024];
    int t = threadIdx.x, b = blockIdx.x;

    for (int e = b * 1024 + t; e < E; e += nb * 1024) {
        int d = dst[e];
        unsigned long long pk = (1ULL << 40)
            | (unsigned long long)__float2uint_rn(ew[e] * 16777216.0f);
        atomicAdd(&g_cd[d], pk);
    }
    gsync(nb);

    int i = b * 1024 + t;
    unsigned long long cd = (i < N) ? g_cd[i] : 0ULL;
    int x = (int)(cd >> 40);
    sm[t] = x;
    __syncthreads();
    for (int o = 1; o < 1024; o <<= 1) {
        int v = (t >= o) ? sm[t - o] : 0;
        __syncthreads();
        sm[t] += v;
        __syncthreads();
    }
    if (i < N) {
        g_rs[i] = sm[t] - x;
        float deg = 1.0f + (float)(cd & 0xFFFFFFFFFFULL) * (1.0f / 16777216.0f);
        g_dinv[i] = rsqrtf(deg);
    }
    if (t == 1023) g_bsum[b] = sm[1023];
    gsync(2 * nb);

    if (b == 0) {
        int y = (t < nb) ? g_bsum[t] : 0;
        sm[t] = y;
        __syncthreads();
        for (int o = 1; o < 1024; o <<= 1) {
            int v = (t >= o) ? sm[t - o] : 0;
            __syncthreads();
            sm[t] += v;
            __syncthreads();
        }
        if (t < nb) g_bsumP[t] = sm[t] - y;
    }
}

// ---------------- launch 2: CSR fill (stores dinv[src]*ew) ----------------
__global__ void k_fill(const int* __restrict__ src, const int* __restrict__ dst,
                       const float* __restrict__ ew, int E) {
    for (int e = blockIdx.x * blockDim.x + threadIdx.x; e < E; e += gridDim.x * blockDim.x) {
        int d = dst[e];
        int s = src[e];
        int p = g_rs[d] + g_bsumP[d >> 10] + atomicAdd(&g_cnt2[d], 1);
        g_csr[p] = make_int2(s, __float_as_int(g_dinv[s] * ew[e]));
    }
}

// ---- launch 3/4: fused conv (all-fp16 features): a = S h; y = a@W+b; LN; ReLU; +h --
// Gather: 16-lane group per node (R5 structure).
__global__ __launch_bounds__(256) void k_conv(const uint2* __restrict__ hh,
                                              const float* __restrict__ W,
                                              const float* __restrict__ bconv,
                                              const float* __restrict__ gam,
                                              const float* __restrict__ bet,
                                              uint2* __restrict__ outh,
                                              int N, int E) {
    __shared__ __align__(16) float Xs[64][68];
    __shared__ __align__(16) float Ws[64][68];
    int t = threadIdx.x;
    int row0 = blockIdx.x * 64;

    const float4* W4 = (const float4*)W;
    for (int i = t; i < 1024; i += 256)
        *(float4*)&Ws[i >> 4][(i & 15) << 2] = W4[i];

    int g = t & 15;
    for (int pass = 0; pass < 4; pass++) {
        int nl = pass * 16 + (t >> 4);
        int node = row0 + nl;
        float4 acc = make_float4(0.f, 0.f, 0.f, 0.f);
        float dvd = 0.f;
        float4 hs = acc;
        if (node < N) {
            dvd = g_dinv[node];
            hs  = unpack4h(hh[node * 16 + g]);
            int e0 = g_rs[node] + g_bsumP[node >> 10];
            int e1 = (node + 1 < N) ? (g_rs[node + 1] + g_bsumP[(node + 1) >> 10]) : E;
            int e  = e0;
            if (e < e1 && (e & 1)) {
                int2 ce = g_csr[e];
                acc_h(acc, __int_as_float(ce.y), hh[ce.x * 16 + g]);
                e++;
            }
            int npairs = (e1 - e) >> 1;
            const int4* c4p = (const int4*)(g_csr + e);
            int i = 0;
            for (; i + 2 <= npairs; i += 2) {
                int4 ca = c4p[i];
                int4 cb = c4p[i + 1];
                uint2 p0 = hh[ca.x * 16 + g];
                uint2 p1 = hh[ca.z * 16 + g];
                uint2 p2 = hh[cb.x * 16 + g];
                uint2 p3 = hh[cb.z * 16 + g];
                acc_h(acc, __int_as_float(ca.y), p0);
                acc_h(acc, __int_as_float(ca.w), p1);
                acc_h(acc, __int_as_float(cb.y), p2);
                acc_h(acc, __int_as_float(cb.w), p3);
            }
            for (; i < npairs; i++) {
                int4 ca = c4p[i];
                uint2 p0 = hh[ca.x * 16 + g];
                uint2 p1 = hh[ca.z * 16 + g];
                acc_h(acc, __int_as_float(ca.y), p0);
                acc_h(acc, __int_as_float(ca.w), p1);
            }
            if ((e1 - e) & 1) {
                int2 ce = g_csr[e1 - 1];
                acc_h(acc, __int_as_float(ce.y), hh[ce.x * 16 + g]);
            }
        }
        float4 a;
        a.x = dvd * (acc.x + dvd * hs.x);
        a.y = dvd * (acc.y + dvd * hs.y);
        a.z = dvd * (acc.z + dvd * hs.z);
        a.w = dvd * (acc.w + dvd * hs.w);
        *(float4*)&Xs[nl][g << 2] = a;
    }
    __syncthreads();

    // GEMM: thread = 1 row x 16 cols
    int r  = t >> 2;
    int cb = (t & 3) << 4;
    float4 a0 = make_float4(0.f,0.f,0.f,0.f), a1 = a0, a2 = a0, a3 = a0;
#pragma unroll
    for (int k = 0; k < 64; k++) {
        float xv = Xs[r][k];
        fma4(a0, xv, *(const float4*)&Ws[k][cb +  0]);
        fma4(a1, xv, *(const float4*)&Ws[k][cb +  4]);
        fma4(a2, xv, *(const float4*)&Ws[k][cb +  8]);
        fma4(a3, xv, *(const float4*)&Ws[k][cb + 12]);
    }

    const float4* b4 = (const float4*)bconv;
    int c4 = cb >> 2;
    float4 q;
    q = b4[c4+0]; a0.x+=q.x; a0.y+=q.y; a0.z+=q.z; a0.w+=q.w;
    q = b4[c4+1]; a1.x+=q.x; a1.y+=q.y; a1.z+=q.z; a1.w+=q.w;
    q = b4[c4+2]; a2.x+=q.x; a2.y+=q.y; a2.z+=q.z; a2.w+=q.w;
    q = b4[c4+3]; a3.x+=q.x; a3.y+=q.y; a3.z+=q.z; a3.w+=q.w;

    // LayerNorm over 64 (4 lanes x 16)
    int lane = t & 31;
    unsigned mask4 = 0xFu << (lane & ~3);
    float s = (a0.x+a0.y+a0.z+a0.w) + (a1.x+a1.y+a1.z+a1.w)
            + (a2.x+a2.y+a2.z+a2.w) + (a3.x+a3.y+a3.z+a3.w);
    s += __shfl_xor_sync(mask4, s, 1, 4);
    s += __shfl_xor_sync(mask4, s, 2, 4);
    float m = s * (1.0f / 64.0f);
    a0.x-=m; a0.y-=m; a0.z-=m; a0.w-=m;
    a1.x-=m; a1.y-=m; a1.z-=m; a1.w-=m;
    a2.x-=m; a2.y-=m; a2.z-=m; a2.w-=m;
    a3.x-=m; a3.y-=m; a3.z-=m; a3.w-=m;
    float vs = (a0.x*a0.x+a0.y*a0.y+a0.z*a0.z+a0.w*a0.w)
             + (a1.x*a1.x+a1.y*a1.y+a1.z*a1.z+a1.w*a1.w)
             + (a2.x*a2.x+a2.y*a2.y+a2.z*a2.z+a2.w*a2.w)
             + (a3.x*a3.x+a3.y*a3.y+a3.z*a3.z+a3.w*a3.w);
    vs += __shfl_xor_sync(mask4, vs, 1, 4);
    vs += __shfl_xor_sync(mask4, vs, 2, 4);
    float rstd = rsqrtf(vs * (1.0f / 64.0f) + 1e-5f);

    const float4* g4  = (const float4*)gam;
    const float4* be4 = (const float4*)bet;
    int grow = row0 + r;
    if (grow < N) {
        int o = grow * 16 + c4;
        float4 gg, be, hi, ov;
        gg = g4[c4+0]; be = be4[c4+0]; hi = unpack4h(hh[o+0]);
        ov.x = fmaxf(a0.x*rstd*gg.x + be.x, 0.f) + hi.x;
        ov.y = fmaxf(a0.y*rstd*gg.y + be.y, 0.f) + hi.y;
        ov.z = fmaxf(a0.z*rstd*gg.z + be.z, 0.f) + hi.z;
        ov.w = fmaxf(a0.w*rstd*gg.w + be.w, 0.f) + hi.w;
        outh[o+0] = pack4h(ov);
        gg = g4[c4+1]; be = be4[c4+1]; hi = unpack4h(hh[o+1]);
        ov.x = fmaxf(a1.x*rstd*gg.x + be.x, 0.f) + hi.x;
        ov.y = fmaxf(a1.y*rstd*gg.y + be.y, 0.f) + hi.y;
        ov.z = fmaxf(a1.z*rstd*gg.z + be.z, 0.f) + hi.z;
        ov.w = fmaxf(a1.w*rstd*gg.w + be.w, 0.f) + hi.w;
        outh[o+1] = pack4h(ov);
        gg = g4[c4+2]; be = be4[c4+2]; hi = unpack4h(hh[o+2]);
        ov.x = fmaxf(a2.x*rstd*gg.x + be.x, 0.f) + hi.x;
        ov.y = fmaxf(a2.y*rstd*gg.y + be.y, 0.f) + hi.y;
        ov.z = fmaxf(a2.z*rstd*gg.z + be.z, 0.f) + hi.z;
        ov.w = fmaxf(a2.w*rstd*gg.w + be.w, 0.f) + hi.w;
        outh[o+2] = pack4h(ov);
        gg = g4[c4+3]; be = be4[c4+3]; hi = unpack4h(hh[o+3]);
        ov.x = fmaxf(a3.x*rstd*gg.x + be.x, 0.f) + hi.x;
        ov.y = fmaxf(a3.y*rstd*gg.y + be.y, 0.f) + hi.y;
        ov.z = fmaxf(a3.z*rstd*gg.z + be.z, 0.f) + hi.z;
        ov.w = fmaxf(a3.w*rstd*gg.w + be.w, 0.f) + hi.w;
        outh[o+3] = pack4h(ov);
    }
}

// ---- launch 5: fused projection + scoring over the 64 pairs of this block ----
// s[p] = clip(<hp[u], hp[NU+i]> + bu + bi + mu), hp[x] = h[x]@Wp + bp
__global__ __launch_bounds__(256) void k_proj_score(const uint2* __restrict__ hh,
                                                    const float* __restrict__ Wp,
                                                    const float* __restrict__ bp,
                                                    const int* __restrict__ users,
                                                    const int* __restrict__ items,
                                                    const float* __restrict__ bu,
                                                    const float* __restrict__ bi,
                                                    const float* __restrict__ mu,
                                                    float* __restrict__ out, int NU) {
    __shared__ __align__(16) float Xs[64][68];
    __shared__ __align__(16) float Ws[64][68];
    int t = threadIdx.x;
    int p0 = blockIdx.x * 64;
    int g = t & 15;

    const float4* W4 = (const float4*)Wp;
    for (int i = t; i < 1024; i += 256)
        *(float4*)&Ws[i >> 4][(i & 15) << 2] = W4[i];

    // gather user rows (fp16 -> fp32)
    for (int pass = 0; pass < 4; pass++) {
        int pl = pass * 16 + (t >> 4);
        int u = users[p0 + pl];
        *(float4*)&Xs[pl][g << 2] = unpack4h(hh[u * 16 + g]);
    }
    __syncthreads();

    int r  = t >> 2;
    int cb = (t & 3) << 4;
    int c4 = cb >> 2;

    // user projection: 16 cols per thread
    float4 u0 = make_float4(0.f,0.f,0.f,0.f), u1 = u0, u2 = u0, u3 = u0;
#pragma unroll
    for (int k = 0; k < 64; k++) {
        float xv = Xs[r][k];
        fma4(u0, xv, *(const float4*)&Ws[k][cb +  0]);
        fma4(u1, xv, *(const float4*)&Ws[k][cb +  4]);
        fma4(u2, xv, *(const float4*)&Ws[k][cb +  8]);
        fma4(u3, xv, *(const float4*)&Ws[k][cb + 12]);
    }
    __syncthreads();

    // gather item rows
    for (int pass = 0; pass < 4; pass++) {
        int pl = pass * 16 + (t >> 4);
        int it = items[p0 + pl];
        *(float4*)&Xs[pl][g << 2] = unpack4h(hh[(NU + it) * 16 + g]);
    }
    __syncthreads();

    // item projection
    float4 i0 = make_float4(0.f,0.f,0.f,0.f), i1 = i0, i2 = i0, i3 = i0;
#pragma unroll
    for (int k = 0; k < 64; k++) {
        float xv = Xs[r][k];
        fma4(i0, xv, *(const float4*)&Ws[k][cb +  0]);
        fma4(i1, xv, *(const float4*)&Ws[k][cb +  4]);
        fma4(i2, xv, *(const float4*)&Ws[k][cb +  8]);
        fma4(i3, xv, *(const float4*)&Ws[k][cb + 12]);
    }

    // + bp to both, dot partial over this thread's 16 cols
    const float4* b4 = (const float4*)bp;
    float4 q;
    float d = 0.f;
    q = b4[c4+0];
    d += (u0.x+q.x)*(i0.x+q.x) + (u0.y+q.y)*(i0.y+q.y)
       + (u0.z+q.z)*(i0.z+q.z) + (u0.w+q.w)*(i0.w+q.w);
    q = b4[c4+1];
    d += (u1.x+q.x)*(i1.x+q.x) + (u1.y+q.y)*(i1.y+q.y)
       + (u1.z+q.z)*(i1.z+q.z) + (u1.w+q.w)*(i1.w+q.w);
    q = b4[c4+2];
    d += (u2.x+q.x)*(i2.x+q.x) + (u2.y+q.y)*(i2.y+q.y)
       + (u2.z+q.z)*(i2.z+q.z) + (u2.w+q.w)*(i2.w+q.w);
    q = b4[c4+3];
    d += (u3.x+q.x)*(i3.x+q.x) + (u3.y+q.y)*(i3.y+q.y)
       + (u3.z+q.z)*(i3.z+q.z) + (u3.w+q.w)*(i3.w+q.w);

    int lane = t & 31;
    unsigned mask4 = 0xFu << (lane & ~3);
    d += __shfl_xor_sync(mask4, d, 1, 4);
    d += __shfl_xor_sync(mask4, d, 2, 4);

    if ((t & 3) == 0) {
        int p = p0 + r;
        float sc = d + bu[users[p]] + bi[items[p]] + mu[0];
        out[p] = fminf(fmaxf(sc, 1.0f), 5.0f);
    }
}

// ---------------- launch ----------------
extern "C" void kernel_launch(void* const* d_in, const int* in_sizes, int n_in,
                              void* d_out, int out_size) {
    const int*    users = (const int*)d_in[0];
    const int*    items = (const int*)d_in[1];
    const int*    eidx  = (const int*)d_in[2];
    const float*  ew    = (const float*)d_in[3];
    const float4* U     = (const float4*)d_in[4];
    const float4* I     = (const float4*)d_in[5];
    const float*  W0    = (const float*)d_in[6];
    const float*  b0    = (const float*)d_in[7];
    const float*  g0    = (const float*)d_in[8];
    const float*  be0   = (const float*)d_in[9];
    const float*  W1    = (const float*)d_in[10];
    const float*  b1    = (const float*)d_in[11];
    const float*  g1    = (const float*)d_in[12];
    const float*  be1   = (const float*)d_in[13];
    const float*  Wp    = (const float*)d_in[14];
    const float*  bp    = (const float*)d_in[15];
    const float*  bu    = (const float*)d_in[16];
    const float*  bi    = (const float*)d_in[17];
    const float*  mu    = (const float*)d_in[18];
    float* out = (float*)d_out;

    int B  = in_sizes[0];
    int E  = in_sizes[3];
    int NU = in_sizes[16];
    int NI = in_sizes[17];
    int N  = NU + NI;
    const int* esrc = eidx;
    const int* edst = eidx + E;

    uint2 *p_hh, *p_hh2;
    cudaGetSymbolAddress((void**)&p_hh,  g_hh);
    cudaGetSymbolAddress((void**)&p_hh2, g_hh2);

    int nb = (N + 1023) / 1024;   // 147 blocks: single wave

    k_concat <<<(N * 16 + 255) / 256, 256>>>(U, I, NU * 16, N * 16, N);
    k_cntscan<<<nb, 1024>>>(edst, ew, E, N, nb);
    k_fill   <<<2048, 256>>>(esrc, edst, ew, E);
    // launch 3 <-- ncu profiles this
    k_conv   <<<(N + 63) / 64, 256>>>(p_hh,  W0, b0, g0, be0, p_hh2, N, E);
    k_conv   <<<(N + 63) / 64, 256>>>(p_hh2, W1, b1, g1, be1, p_hh,  N, E);
    k_proj_score<<<B / 64, 256>>>(p_hh, Wp, bp, users, items, bu, bi, mu, out, NU);
}

// round 12
// speedup vs baseline: 1.4678x; 1.4678x over previous
#include <cuda_runtime.h>
#include <cuda_fp16.h>
#include <math.h>

#define NMAX 150016
#define EMAX 3200064

// ---------------- static device scratch ----------------
__device__ float  g_dinv[NMAX];
__device__ unsigned long long g_cd[NMAX];   // count<<40 | sum(w * 2^24)
__device__ int    g_cnt2[NMAX];
__device__ int    g_rs[NMAX + 2];
__device__ int    g_bsum[1024];
__device__ int    g_bsumP[1024];
__device__ int    g_bar;
__device__ __align__(16) int2 g_csr[EMAX];  // {src, dinv[src]*ew bits}
__device__ float4 g_hw[NMAX * 16];          // scratch (aliased as fp16 buf2)
__device__ float4 g_h [NMAX * 16];          // fp32 features ping
__device__ float4 g_h2[NMAX * 16];          // fp32 features pong
__device__ uint2  g_hh[NMAX * 16];          // fp16 gather copy

__device__ __forceinline__ void fma4(float4& a, float s, const float4& w) {
    a.x += s * w.x; a.y += s * w.y; a.z += s * w.z; a.w += s * w.w;
}
__device__ __forceinline__ uint2 pack4h(const float4& v) {
    __half2 lo = __float22half2_rn(make_float2(v.x, v.y));
    __half2 hi = __float22half2_rn(make_float2(v.z, v.w));
    uint2 r;
    r.x = *(const unsigned*)&lo;
    r.y = *(const unsigned*)&hi;
    return r;
}
__device__ __forceinline__ void acc_h(float4& acc, float ww, const uint2& pv) {
    float2 f0 = __half22float2(*(const __half2*)&pv.x);
    float2 f1 = __half22float2(*(const __half2*)&pv.y);
    acc.x += ww * f0.x; acc.y += ww * f0.y;
    acc.z += ww * f1.x; acc.w += ww * f1.y;
}

// ---------------- launch 0: concat x=[U;I] + zero counters ----------------
__global__ void k_concat(const float4* __restrict__ U, const float4* __restrict__ I,
                         int nu16, int tot16, int N) {
    int i = blockIdx.x * blockDim.x + threadIdx.x;
    if (i < tot16) {
        float4 v = (i < nu16) ? U[i] : I[i - nu16];
        g_h[i]  = v;
        g_hh[i] = pack4h(v);
    }
    if (i < N) { g_cd[i] = 0ULL; g_cnt2[i] = 0; }
    if (i == 0) g_bar = 0;
}

// ---------------- software grid barrier (single-wave persistent kernel) -------
__device__ __forceinline__ void gsync(int target) {
    __syncthreads();
    __threadfence();
    if (threadIdx.x == 0) {
        atomicAdd(&g_bar, 1);
        while (atomicAdd(&g_bar, 0) < target) { }
        __threadfence();
    }
    __syncthreads();
}

// ---- launch 1: fused count (packed 64-bit atomic) + scan + dinv + block offsets ----
__global__ __launch_bounds__(1024) void k_cntscan(const int* __restrict__ dst,
                                                  const float* __restrict__ ew,
                                                  int E, int N, int nb) {
    __shared__ int sm[1024];
    int t = threadIdx.x, b = blockIdx.x;

    for (int e = b * 1024 + t; e < E; e += nb * 1024) {
        int d = dst[e];
        unsigned long long pk = (1ULL << 40)
            | (unsigned long long)__float2uint_rn(ew[e] * 16777216.0f);
        atomicAdd(&g_cd[d], pk);
    }
    gsync(nb);

    int i = b * 1024 + t;
    unsigned long long cd = (i < N) ? g_cd[i] : 0ULL;
    int x = (int)(cd >> 40);
    sm[t] = x;
    __syncthreads();
    for (int o = 1; o < 1024; o <<= 1) {
        int v = (t >= o) ? sm[t - o] : 0;
        __syncthreads();
        sm[t] += v;
        __syncthreads();
    }
    if (i < N) {
        g_rs[i] = sm[t] - x;
        float deg = 1.0f + (float)(cd & 0xFFFFFFFFFFULL) * (1.0f / 16777216.0f);
        g_dinv[i] = rsqrtf(deg);
    }
    if (t == 1023) g_bsum[b] = sm[1023];
    gsync(2 * nb);

    if (b == 0) {
        int y = (t < nb) ? g_bsum[t] : 0;
        sm[t] = y;
        __syncthreads();
        for (int o = 1; o < 1024; o <<= 1) {
            int v = (t >= o) ? sm[t - o] : 0;
            __syncthreads();
            sm[t] += v;
            __syncthreads();
        }
        if (t < nb) g_bsumP[t] = sm[t] - y;
    }
}

// ---------------- launch 2: CSR fill (stores dinv[src]*ew) ----------------
__global__ void k_fill(const int* __restrict__ src, const int* __restrict__ dst,
                       const float* __restrict__ ew, int E) {
    for (int e = blockIdx.x * blockDim.x + threadIdx.x; e < E; e += gridDim.x * blockDim.x) {
        int d = dst[e];
        int s = src[e];
        int p = g_rs[d] + g_bsumP[d >> 10] + atomicAdd(&g_cnt2[d], 1);
        g_csr[p] = make_int2(s, __float_as_int(g_dinv[s] * ew[e]));
    }
}

// ---- launch 3/4: fused conv: a = S h; y = a@W + b; LN; ReLU; +h ----
// (R5 structure: 16-lane group per node, fp16 gather, fp32 residual; 8-deep unroll)
__global__ __launch_bounds__(256) void k_conv(const float4* __restrict__ h,
                                              const uint2*  __restrict__ hh,
                                              const float* __restrict__ W,
                                              const float* __restrict__ bconv,
                                              const float* __restrict__ gam,
                                              const float* __restrict__ bet,
                                              float4* __restrict__ out,
                                              uint2*  __restrict__ outh,
                                              int N, int E) {
    __shared__ __align__(16) float Xs[64][68];
    __shared__ __align__(16) float Ws[64][68];
    int t = threadIdx.x;
    int row0 = blockIdx.x * 64;

    const float4* W4 = (const float4*)W;
    for (int i = t; i < 1024; i += 256)
        *(float4*)&Ws[i >> 4][(i & 15) << 2] = W4[i];

    int g = t & 15;
    for (int pass = 0; pass < 4; pass++) {
        int nl = pass * 16 + (t >> 4);
        int node = row0 + nl;
        float4 acc = make_float4(0.f, 0.f, 0.f, 0.f);
        float dvd = 0.f;
        float4 hs = acc;
        if (node < N) {
            dvd = g_dinv[node];
            hs  = h[node * 16 + g];
            int e0 = g_rs[node] + g_bsumP[node >> 10];
            int e1 = (node + 1 < N) ? (g_rs[node + 1] + g_bsumP[(node + 1) >> 10]) : E;
            int e  = e0;
            if (e < e1 && (e & 1)) {
                int2 ce = g_csr[e];
                acc_h(acc, __int_as_float(ce.y), hh[ce.x * 16 + g]);
                e++;
            }
            int npairs = (e1 - e) >> 1;
            const int4* c4p = (const int4*)(g_csr + e);
            int i = 0;
            // 8 edges per iter: 4 int4 CSR loads + 8 independent hh loads in flight
            for (; i + 4 <= npairs; i += 4) {
                int4 ca = c4p[i];
                int4 cb = c4p[i + 1];
                int4 cc = c4p[i + 2];
                int4 cd = c4p[i + 3];
                uint2 p0 = hh[ca.x * 16 + g];
                uint2 p1 = hh[ca.z * 16 + g];
                uint2 p2 = hh[cb.x * 16 + g];
                uint2 p3 = hh[cb.z * 16 + g];
                uint2 p4 = hh[cc.x * 16 + g];
                uint2 p5 = hh[cc.z * 16 + g];
                uint2 p6 = hh[cd.x * 16 + g];
                uint2 p7 = hh[cd.z * 16 + g];
                acc_h(acc, __int_as_float(ca.y), p0);
                acc_h(acc, __int_as_float(ca.w), p1);
                acc_h(acc, __int_as_float(cb.y), p2);
                acc_h(acc, __int_as_float(cb.w), p3);
                acc_h(acc, __int_as_float(cc.y), p4);
                acc_h(acc, __int_as_float(cc.w), p5);
                acc_h(acc, __int_as_float(cd.y), p6);
                acc_h(acc, __int_as_float(cd.w), p7);
            }
            for (; i < npairs; i++) {
                int4 ca = c4p[i];
                uint2 p0 = hh[ca.x * 16 + g];
                uint2 p1 = hh[ca.z * 16 + g];
                acc_h(acc, __int_as_float(ca.y), p0);
                acc_h(acc, __int_as_float(ca.w), p1);
            }
            if ((e1 - e) & 1) {
                int2 ce = g_csr[e1 - 1];
                acc_h(acc, __int_as_float(ce.y), hh[ce.x * 16 + g]);
            }
        }
        float4 a;
        a.x = dvd * (acc.x + dvd * hs.x);
        a.y = dvd * (acc.y + dvd * hs.y);
        a.z = dvd * (acc.z + dvd * hs.z);
        a.w = dvd * (acc.w + dvd * hs.w);
        *(float4*)&Xs[nl][g << 2] = a;
    }
    __syncthreads();

    // GEMM: thread = 1 row x 16 cols
    int r  = t >> 2;
    int cb = (t & 3) << 4;
    float4 a0 = make_float4(0.f,0.f,0.f,0.f), a1 = a0, a2 = a0, a3 = a0;
#pragma unroll
    for (int k = 0; k < 64; k++) {
        float xv = Xs[r][k];
        fma4(a0, xv, *(const float4*)&Ws[k][cb +  0]);
        fma4(a1, xv, *(const float4*)&Ws[k][cb +  4]);
        fma4(a2, xv, *(const float4*)&Ws[k][cb +  8]);
        fma4(a3, xv, *(const float4*)&Ws[k][cb + 12]);
    }

    const float4* b4 = (const float4*)bconv;
    int c4 = cb >> 2;
    float4 q;
    q = b4[c4+0]; a0.x+=q.x; a0.y+=q.y; a0.z+=q.z; a0.w+=q.w;
    q = b4[c4+1]; a1.x+=q.x; a1.y+=q.y; a1.z+=q.z; a1.w+=q.w;
    q = b4[c4+2]; a2.x+=q.x; a2.y+=q.y; a2.z+=q.z; a2.w+=q.w;
    q = b4[c4+3]; a3.x+=q.x; a3.y+=q.y; a3.z+=q.z; a3.w+=q.w;

    // LayerNorm over 64 (4 lanes x 16)
    int lane = t & 31;
    unsigned mask4 = 0xFu << (lane & ~3);
    float s = (a0.x+a0.y+a0.z+a0.w) + (a1.x+a1.y+a1.z+a1.w)
            + (a2.x+a2.y+a2.z+a2.w) + (a3.x+a3.y+a3.z+a3.w);
    s += __shfl_xor_sync(mask4, s, 1, 4);
    s += __shfl_xor_sync(mask4, s, 2, 4);
    float m = s * (1.0f / 64.0f);
    a0.x-=m; a0.y-=m; a0.z-=m; a0.w-=m;
    a1.x-=m; a1.y-=m; a1.z-=m; a1.w-=m;
    a2.x-=m; a2.y-=m; a2.z-=m; a2.w-=m;
    a3.x-=m; a3.y-=m; a3.z-=m; a3.w-=m;
    float vs = (a0.x*a0.x+a0.y*a0.y+a0.z*a0.z+a0.w*a0.w)
             + (a1.x*a1.x+a1.y*a1.y+a1.z*a1.z+a1.w*a1.w)
             + (a2.x*a2.x+a2.y*a2.y+a2.z*a2.z+a2.w*a2.w)
             + (a3.x*a3.x+a3.y*a3.y+a3.z*a3.z+a3.w*a3.w);
    vs += __shfl_xor_sync(mask4, vs, 1, 4);
    vs += __shfl_xor_sync(mask4, vs, 2, 4);
    float rstd = rsqrtf(vs * (1.0f / 64.0f) + 1e-5f);

    const float4* g4  = (const float4*)gam;
    const float4* be4 = (const float4*)bet;
    int grow = row0 + r;
    if (grow < N) {
        int o = grow * 16 + c4;
        float4 gg, be, hi, ov;
        gg = g4[c4+0]; be = be4[c4+0]; hi = h[o+0];
        ov.x = fmaxf(a0.x*rstd*gg.x + be.x, 0.f) + hi.x;
        ov.y = fmaxf(a0.y*rstd*gg.y + be.y, 0.f) + hi.y;
        ov.z = fmaxf(a0.z*rstd*gg.z + be.z, 0.f) + hi.z;
        ov.w = fmaxf(a0.w*rstd*gg.w + be.w, 0.f) + hi.w;
        out[o+0] = ov; outh[o+0] = pack4h(ov);
        gg = g4[c4+1]; be = be4[c4+1]; hi = h[o+1];
        ov.x = fmaxf(a1.x*rstd*gg.x + be.x, 0.f) + hi.x;
        ov.y = fmaxf(a1.y*rstd*gg.y + be.y, 0.f) + hi.y;
        ov.z = fmaxf(a1.z*rstd*gg.z + be.z, 0.f) + hi.z;
        ov.w = fmaxf(a1.w*rstd*gg.w + be.w, 0.f) + hi.w;
        out[o+1] = ov; outh[o+1] = pack4h(ov);
        gg = g4[c4+2]; be = be4[c4+2]; hi = h[o+2];
        ov.x = fmaxf(a2.x*rstd*gg.x + be.x, 0.f) + hi.x;
        ov.y = fmaxf(a2.y*rstd*gg.y + be.y, 0.f) + hi.y;
        ov.z = fmaxf(a2.z*rstd*gg.z + be.z, 0.f) + hi.z;
        ov.w = fmaxf(a2.w*rstd*gg.w + be.w, 0.f) + hi.w;
        out[o+2] = ov; outh[o+2] = pack4h(ov);
        gg = g4[c4+3]; be = be4[c4+3]; hi = h[o+3];
        ov.x = fmaxf(a3.x*rstd*gg.x + be.x, 0.f) + hi.x;
        ov.y = fmaxf(a3.y*rstd*gg.y + be.y, 0.f) + hi.y;
        ov.z = fmaxf(a3.z*rstd*gg.z + be.z, 0.f) + hi.z;
        ov.w = fmaxf(a3.w*rstd*gg.w + be.w, 0.f) + hi.w;
        out[o+3] = ov; outh[o+3] = pack4h(ov);
    }
}

// ---- launch 5: fused projection + scoring (reads fp32 features) ----
__global__ __launch_bounds__(256) void k_proj_score(const float4* __restrict__ h,
                                                    const float* __restrict__ Wp,
                                                    const float* __restrict__ bp,
                                                    const int* __restrict__ users,
                                                    const int* __restrict__ items,
                                                    const float* __restrict__ bu,
                                                    const float* __restrict__ bi,
                                                    const float* __restrict__ mu,
                                                    float* __restrict__ out, int NU) {
    __shared__ __align__(16) float Xs[64][68];
    __shared__ __align__(16) float Ws[64][68];
    int t = threadIdx.x;
    int p0 = blockIdx.x * 64;
    int g = t & 15;

    const float4* W4 = (const float4*)Wp;
    for (int i = t; i < 1024; i += 256)
        *(float4*)&Ws[i >> 4][(i & 15) << 2] = W4[i];

    // gather user rows
    for (int pass = 0; pass < 4; pass++) {
        int pl = pass * 16 + (t >> 4);
        int u = users[p0 + pl];
        *(float4*)&Xs[pl][g << 2] = h[u * 16 + g];
    }
    __syncthreads();

    int r  = t >> 2;
    int cb = (t & 3) << 4;
    int c4 = cb >> 2;

    float4 u0 = make_float4(0.f,0.f,0.f,0.f), u1 = u0, u2 = u0, u3 = u0;
#pragma unroll
    for (int k = 0; k < 64; k++) {
        float xv = Xs[r][k];
        fma4(u0, xv, *(const float4*)&Ws[k][cb +  0]);
        fma4(u1, xv, *(const float4*)&Ws[k][cb +  4]);
        fma4(u2, xv, *(const float4*)&Ws[k][cb +  8]);
        fma4(u3, xv, *(const float4*)&Ws[k][cb + 12]);
    }
    __syncthreads();

    // gather item rows
    for (int pass = 0; pass < 4; pass++) {
        int pl = pass * 16 + (t >> 4);
        int it = items[p0 + pl];
        *(float4*)&Xs[pl][g << 2] = h[(NU + it) * 16 + g];
    }
    __syncthreads();

    float4 i0 = make_float4(0.f,0.f,0.f,0.f), i1 = i0, i2 = i0, i3 = i0;
#pragma unroll
    for (int k = 0; k < 64; k++) {
        float xv = Xs[r][k];
        fma4(i0, xv, *(const float4*)&Ws[k][cb +  0]);
        fma4(i1, xv, *(const float4*)&Ws[k][cb +  4]);
        fma4(i2, xv, *(const float4*)&Ws[k][cb +  8]);
        fma4(i3, xv, *(const float4*)&Ws[k][cb + 12]);
    }

    const float4* b4 = (const float4*)bp;
    float4 q;
    float d = 0.f;
    q = b4[c4+0];
    d += (u0.x+q.x)*(i0.x+q.x) + (u0.y+q.y)*(i0.y+q.y)
       + (u0.z+q.z)*(i0.z+q.z) + (u0.w+q.w)*(i0.w+q.w);
    q = b4[c4+1];
    d += (u1.x+q.x)*(i1.x+q.x) + (u1.y+q.y)*(i1.y+q.y)
       + (u1.z+q.z)*(i1.z+q.z) + (u1.w+q.w)*(i1.w+q.w);
    q = b4[c4+2];
    d += (u2.x+q.x)*(i2.x+q.x) + (u2.y+q.y)*(i2.y+q.y)
       + (u2.z+q.z)*(i2.z+q.z) + (u2.w+q.w)*(i2.w+q.w);
    q = b4[c4+3];
    d += (u3.x+q.x)*(i3.x+q.x) + (u3.y+q.y)*(i3.y+q.y)
       + (u3.z+q.z)*(i3.z+q.z) + (u3.w+q.w)*(i3.w+q.w);

    int lane = t & 31;
    unsigned mask4 = 0xFu << (lane & ~3);
    d += __shfl_xor_sync(mask4, d, 1, 4);
    d += __shfl_xor_sync(mask4, d, 2, 4);

    if ((t & 3) == 0) {
        int p = p0 + r;
        float sc = d + bu[users[p]] + bi[items[p]] + mu[0];
        out[p] = fminf(fmaxf(sc, 1.0f), 5.0f);
    }
}

// ---------------- launch ----------------
extern "C" void kernel_launch(void* const* d_in, const int* in_sizes, int n_in,
                              void* d_out, int out_size) {
    const int*    users = (const int*)d_in[0];
    const int*    items = (const int*)d_in[1];
    const int*    eidx  = (const int*)d_in[2];
    const float*  ew    = (const float*)d_in[3];
    const float4* U     = (const float4*)d_in[4];
    const float4* I     = (const float4*)d_in[5];
    const float*  W0    = (const float*)d_in[6];
    const float*  b0    = (const float*)d_in[7];
    const float*  g0    = (const float*)d_in[8];
    const float*  be0   = (const float*)d_in[9];
    const float*  W1    = (const float*)d_in[10];
    const float*  b1    = (const float*)d_in[11];
    const float*  g1    = (const float*)d_in[12];
    const float*  be1   = (const float*)d_in[13];
    const float*  Wp    = (const float*)d_in[14];
    const float*  bp    = (const float*)d_in[15];
    const float*  bu    = (const float*)d_in[16];
    const float*  bi    = (const float*)d_in[17];
    const float*  mu    = (const float*)d_in[18];
    float* out = (float*)d_out;

    int B  = in_sizes[0];
    int E  = in_sizes[3];
    int NU = in_sizes[16];
    int NI = in_sizes[17];
    int N  = NU + NI;
    const int* esrc = eidx;
    const int* edst = eidx + E;

    float4 *p_h, *p_h2, *p_hw;
    uint2  *p_hh, *p_hh2;
    cudaGetSymbolAddress((void**)&p_h,   g_h);
    cudaGetSymbolAddress((void**)&p_h2,  g_h2);
    cudaGetSymbolAddress((void**)&p_hw,  g_hw);
    cudaGetSymbolAddress((void**)&p_hh,  g_hh);
    p_hh2 = (uint2*)p_hw;   // fp16 buffer 2 aliases g_hw scratch

    int nb = (N + 1023) / 1024;   // 147 blocks: single wave

    k_concat <<<(N * 16 + 255) / 256, 256>>>(U, I, NU * 16, N * 16, N);
    k_cntscan<<<nb, 1024>>>(edst, ew, E, N, nb);
    k_fill   <<<2048, 256>>>(esrc, edst, ew, E);
    // launch 3 <-- ncu profiles this
    k_conv   <<<(N + 63) / 64, 256>>>(p_h,  p_hh,  W0, b0, g0, be0, p_h2, p_hh2, N, E);
    k_conv   <<<(N + 63) / 64, 256>>>(p_h2, p_hh2, W1, b1, g1, be1, p_h,  p_hh,  N, E);
    k_proj_score<<<B / 64, 256>>>(p_h, Wp, bp, users, items, bu, bi, mu, out, NU);
}

// round 13
// speedup vs baseline: 2.4170x; 1.6467x over previous
#include <cuda_runtime.h>
#include <cuda_fp16.h>
#include <math.h>

#define NMAX 150016
#define EMAX 3200064

// ---------------- static device scratch ----------------
__device__ float  g_dinv[NMAX];
__device__ unsigned long long g_cd[NMAX];   // count<<40 | sum(w * 2^24)
__device__ int    g_cnt2[NMAX];
__device__ int    g_rs[NMAX + 2];
__device__ int    g_bsum[1024];
__device__ int    g_bsumP[1024];
__device__ int    g_bar;
__device__ __align__(16) int2 g_csr[EMAX];  // {src, dinv[src]*ew bits}
__device__ float4 g_hw[NMAX * 16];          // scratch (aliased as fp16 buf2)
__device__ float4 g_h [NMAX * 16];          // fp32 features ping
__device__ float4 g_h2[NMAX * 16];          // fp32 features pong
__device__ uint2  g_hh[NMAX * 16];          // fp16 gather copy

__device__ __forceinline__ void fma4(float4& a, float s, const float4& w) {
    a.x += s * w.x; a.y += s * w.y; a.z += s * w.z; a.w += s * w.w;
}
__device__ __forceinline__ uint2 pack4h(const float4& v) {
    __half2 lo = __float22half2_rn(make_float2(v.x, v.y));
    __half2 hi = __float22half2_rn(make_float2(v.z, v.w));
    uint2 r;
    r.x = *(const unsigned*)&lo;
    r.y = *(const unsigned*)&hi;
    return r;
}
__device__ __forceinline__ void acc_h(float4& acc, float ww, const uint2& pv) {
    float2 f0 = __half22float2(*(const __half2*)&pv.x);
    float2 f1 = __half22float2(*(const __half2*)&pv.y);
    acc.x += ww * f0.x; acc.y += ww * f0.y;
    acc.z += ww * f1.x; acc.w += ww * f1.y;
}
__device__ __forceinline__ unsigned smem_u32(const void* p) {
    return (unsigned)__cvta_generic_to_shared(p);
}

// ---------------- launch 0: concat x=[U;I] + zero counters ----------------
__global__ void k_concat(const float4* __restrict__ U, const float4* __restrict__ I,
                         int nu16, int tot16, int N) {
    int i = blockIdx.x * blockDim.x + threadIdx.x;
    if (i < tot16) {
        float4 v = (i < nu16) ? U[i] : I[i - nu16];
        g_h[i]  = v;
        g_hh[i] = pack4h(v);
    }
    if (i < N) { g_cd[i] = 0ULL; g_cnt2[i] = 0; }
    if (i == 0) g_bar = 0;
}

// ---------------- software grid barrier (single-wave persistent kernel) -------
__device__ __forceinline__ void gsync(int target) {
    __syncthreads();
    __threadfence();
    if (threadIdx.x == 0) {
        atomicAdd(&g_bar, 1);
        while (atomicAdd(&g_bar, 0) < target) { }
        __threadfence();
    }
    __syncthreads();
}

// ---- launch 1: fused count (packed 64-bit atomic) + scan + dinv + block offsets ----
__global__ __launch_bounds__(1024) void k_cntscan(const int* __restrict__ dst,
                                                  const float* __restrict__ ew,
                                                  int E, int N, int nb) {
    __shared__ int sm[1024];
    int t = threadIdx.x, b = blockIdx.x;

    for (int e = b * 1024 + t; e < E; e += nb * 1024) {
        int d = dst[e];
        unsigned long long pk = (1ULL << 40)
            | (unsigned long long)__float2uint_rn(ew[e] * 16777216.0f);
        atomicAdd(&g_cd[d], pk);
    }
    gsync(nb);

    int i = b * 1024 + t;
    unsigned long long cd = (i < N) ? g_cd[i] : 0ULL;
    int x = (int)(cd >> 40);
    sm[t] = x;
    __syncthreads();
    for (int o = 1; o < 1024; o <<= 1) {
        int v = (t >= o) ? sm[t - o] : 0;
        __syncthreads();
        sm[t] += v;
        __syncthreads();
    }
    if (i < N) {
        g_rs[i] = sm[t] - x;
        float deg = 1.0f + (float)(cd & 0xFFFFFFFFFFULL) * (1.0f / 16777216.0f);
        g_dinv[i] = rsqrtf(deg);
    }
    if (t == 1023) g_bsum[b] = sm[1023];
    gsync(2 * nb);

    if (b == 0) {
        int y = (t < nb) ? g_bsum[t] : 0;
        sm[t] = y;
        __syncthreads();
        for (int o = 1; o < 1024; o <<= 1) {
            int v = (t >= o) ? sm[t - o] : 0;
            __syncthreads();
            sm[t] += v;
            __syncthreads();
        }
        if (t < nb) g_bsumP[t] = sm[t] - y;
    }
}

// ---------------- launch 2: CSR fill (stores dinv[src]*ew) ----------------
__global__ void k_fill(const int* __restrict__ src, const int* __restrict__ dst,
                       const float* __restrict__ ew, int E) {
    for (int e = blockIdx.x * blockDim.x + threadIdx.x; e < E; e += gridDim.x * blockDim.x) {
        int d = dst[e];
        int s = src[e];
        int p = g_rs[d] + g_bsumP[d >> 10] + atomicAdd(&g_cnt2[d], 1);
        g_csr[p] = make_int2(s, __float_as_int(g_dinv[s] * ew[e]));
    }
}

// ---- launch 3/4: fused conv: a = S h (fp16 gather); y = a@W via HMMA; LN; ReLU; +h --
__global__ __launch_bounds__(256, 4) void k_conv(const float4* __restrict__ h,
                                                 const uint2*  __restrict__ hh,
                                                 const float* __restrict__ W,
                                                 const float* __restrict__ bconv,
                                                 const float* __restrict__ gam,
                                                 const float* __restrict__ bet,
                                                 float4* __restrict__ out,
                                                 uint2*  __restrict__ outh,
                                                 int N, int E) {
    __shared__ __align__(16) __half Xh[64][72];   // aggregated tile, fp16
    __shared__ __align__(16) __half Wh[64][72];   // W, fp16
    __shared__ __align__(16) float  Ys[64][68];   // mma result, fp32
    int t = threadIdx.x;
    int row0 = blockIdx.x * 64;

    // W fp32 -> fp16 smem
    const float4* W4 = (const float4*)W;
    for (int i = t; i < 1024; i += 256) {
        int k = i >> 4, c4 = i & 15;
        *(uint2*)&Wh[k][c4 << 2] = pack4h(W4[i]);
    }

    // gather phase (R12 structure, writes fp16 tile)
    int g = t & 15;
    for (int pass = 0; pass < 4; pass++) {
        int nl = pass * 16 + (t >> 4);
        int node = row0 + nl;
        float4 acc = make_float4(0.f, 0.f, 0.f, 0.f);
        float dvd = 0.f;
        float4 hs = acc;
        if (node < N) {
            dvd = g_dinv[node];
            hs  = h[node * 16 + g];
            int e0 = g_rs[node] + g_bsumP[node >> 10];
            int e1 = (node + 1 < N) ? (g_rs[node + 1] + g_bsumP[(node + 1) >> 10]) : E;
            int e  = e0;
            if (e < e1 && (e & 1)) {
                int2 ce = g_csr[e];
                acc_h(acc, __int_as_float(ce.y), hh[ce.x * 16 + g]);
                e++;
            }
            int npairs = (e1 - e) >> 1;
            const int4* c4p = (const int4*)(g_csr + e);
            int i = 0;
            for (; i + 4 <= npairs; i += 4) {
                int4 ca = c4p[i];
                int4 cb = c4p[i + 1];
                int4 cc = c4p[i + 2];
                int4 cd = c4p[i + 3];
                uint2 p0 = hh[ca.x * 16 + g];
                uint2 p1 = hh[ca.z * 16 + g];
                uint2 p2 = hh[cb.x * 16 + g];
                uint2 p3 = hh[cb.z * 16 + g];
                uint2 p4 = hh[cc.x * 16 + g];
                uint2 p5 = hh[cc.z * 16 + g];
                uint2 p6 = hh[cd.x * 16 + g];
                uint2 p7 = hh[cd.z * 16 + g];
                acc_h(acc, __int_as_float(ca.y), p0);
                acc_h(acc, __int_as_float(ca.w), p1);
                acc_h(acc, __int_as_float(cb.y), p2);
                acc_h(acc, __int_as_float(cb.w), p3);
                acc_h(acc, __int_as_float(cc.y), p4);
                acc_h(acc, __int_as_float(cc.w), p5);
                acc_h(acc, __int_as_float(cd.y), p6);
                acc_h(acc, __int_as_float(cd.w), p7);
            }
            for (; i < npairs; i++) {
                int4 ca = c4p[i];
                uint2 p0 = hh[ca.x * 16 + g];
                uint2 p1 = hh[ca.z * 16 + g];
                acc_h(acc, __int_as_float(ca.y), p0);
                acc_h(acc, __int_as_float(ca.w), p1);
            }
            if ((e1 - e) & 1) {
                int2 ce = g_csr[e1 - 1];
                acc_h(acc, __int_as_float(ce.y), hh[ce.x * 16 + g]);
            }
        }
        float4 a;
        a.x = dvd * (acc.x + dvd * hs.x);
        a.y = dvd * (acc.y + dvd * hs.y);
        a.z = dvd * (acc.z + dvd * hs.z);
        a.w = dvd * (acc.w + dvd * hs.w);
        *(uint2*)&Xh[nl][g << 2] = pack4h(a);
    }
    __syncthreads();

    // ---- HMMA GEMM: warps 0-3, each m16 x n64, k=64 ----
    int w = t >> 5, lane = t & 31;
    if (w < 4) {
        float acc[8][4];
#pragma unroll
        for (int nt = 0; nt < 8; nt++) {
            acc[nt][0] = 0.f; acc[nt][1] = 0.f; acc[nt][2] = 0.f; acc[nt][3] = 0.f;
        }
#pragma unroll
        for (int ks = 0; ks < 4; ks++) {
            unsigned a0, a1, a2, a3;
            unsigned aaddr = smem_u32(&Xh[w * 16 + (lane & 15)][ks * 16 + ((lane >> 4) << 3)]);
            asm volatile("ldmatrix.sync.aligned.m8n8.x4.shared.b16 {%0,%1,%2,%3}, [%4];"
                         : "=r"(a0), "=r"(a1), "=r"(a2), "=r"(a3) : "r"(aaddr));
#pragma unroll
            for (int nt = 0; nt < 8; nt += 2) {
                unsigned b0, b1, b2, b3;
                unsigned baddr = smem_u32(&Wh[ks * 16 + (lane & 15)][nt * 8 + ((lane >> 4) << 3)]);
                asm volatile("ldmatrix.sync.aligned.m8n8.x4.trans.shared.b16 {%0,%1,%2,%3}, [%4];"
                             : "=r"(b0), "=r"(b1), "=r"(b2), "=r"(b3) : "r"(baddr));
                asm volatile("mma.sync.aligned.m16n8k16.row.col.f32.f16.f16.f32 "
                             "{%0,%1,%2,%3}, {%4,%5,%6,%7}, {%8,%9}, {%0,%1,%2,%3};"
                             : "+f"(acc[nt][0]), "+f"(acc[nt][1]), "+f"(acc[nt][2]), "+f"(acc[nt][3])
                             : "r"(a0), "r"(a1), "r"(a2), "r"(a3), "r"(b0), "r"(b1));
                asm volatile("mma.sync.aligned.m16n8k16.row.col.f32.f16.f16.f32 "
                             "{%0,%1,%2,%3}, {%4,%5,%6,%7}, {%8,%9}, {%0,%1,%2,%3};"
                             : "+f"(acc[nt+1][0]), "+f"(acc[nt+1][1]), "+f"(acc[nt+1][2]), "+f"(acc[nt+1][3])
                             : "r"(a0), "r"(a1), "r"(a2), "r"(a3), "r"(b2), "r"(b3));
            }
        }
        int r0 = w * 16 + (lane >> 2);
        int c0 = (lane & 3) << 1;
#pragma unroll
        for (int nt = 0; nt < 8; nt++) {
            *(float2*)&Ys[r0    ][nt * 8 + c0] = make_float2(acc[nt][0], acc[nt][1]);
            *(float2*)&Ys[r0 + 8][nt * 8 + c0] = make_float2(acc[nt][2], acc[nt][3]);
        }
    }
    __syncthreads();

    // ---- epilogue: bias + LN + ReLU + residual (reads Ys) ----
    int r  = t >> 2;
    int cb = (t & 3) << 4;
    int c4 = cb >> 2;
    float4 a0 = *(const float4*)&Ys[r][cb +  0];
    float4 a1 = *(const float4*)&Ys[r][cb +  4];
    float4 a2 = *(const float4*)&Ys[r][cb +  8];
    float4 a3 = *(const float4*)&Ys[r][cb + 12];

    const float4* b4 = (const float4*)bconv;
    float4 q;
    q = b4[c4+0]; a0.x+=q.x; a0.y+=q.y; a0.z+=q.z; a0.w+=q.w;
    q = b4[c4+1]; a1.x+=q.x; a1.y+=q.y; a1.z+=q.z; a1.w+=q.w;
    q = b4[c4+2]; a2.x+=q.x; a2.y+=q.y; a2.z+=q.z; a2.w+=q.w;
    q = b4[c4+3]; a3.x+=q.x; a3.y+=q.y; a3.z+=q.z; a3.w+=q.w;

    int lane2 = t & 31;
    unsigned mask4 = 0xFu << (lane2 & ~3);
    float s = (a0.x+a0.y+a0.z+a0.w) + (a1.x+a1.y+a1.z+a1.w)
            + (a2.x+a2.y+a2.z+a2.w) + (a3.x+a3.y+a3.z+a3.w);
    s += __shfl_xor_sync(mask4, s, 1, 4);
    s += __shfl_xor_sync(mask4, s, 2, 4);
    float m = s * (1.0f / 64.0f);
    a0.x-=m; a0.y-=m; a0.z-=m; a0.w-=m;
    a1.x-=m; a1.y-=m; a1.z-=m; a1.w-=m;
    a2.x-=m; a2.y-=m; a2.z-=m; a2.w-=m;
    a3.x-=m; a3.y-=m; a3.z-=m; a3.w-=m;
    float vs = (a0.x*a0.x+a0.y*a0.y+a0.z*a0.z+a0.w*a0.w)
             + (a1.x*a1.x+a1.y*a1.y+a1.z*a1.z+a1.w*a1.w)
             + (a2.x*a2.x+a2.y*a2.y+a2.z*a2.z+a2.w*a2.w)
             + (a3.x*a3.x+a3.y*a3.y+a3.z*a3.z+a3.w*a3.w);
    vs += __shfl_xor_sync(mask4, vs, 1, 4);
    vs += __shfl_xor_sync(mask4, vs, 2, 4);
    float rstd = rsqrtf(vs * (1.0f / 64.0f) + 1e-5f);

    const float4* g4  = (const float4*)gam;
    const float4* be4 = (const float4*)bet;
    int grow = row0 + r;
    if (grow < N) {
        int o = grow * 16 + c4;
        float4 gg, be, hi, ov;
        gg = g4[c4+0]; be = be4[c4+0]; hi = h[o+0];
        ov.x = fmaxf(a0.x*rstd*gg.x + be.x, 0.f) + hi.x;
        ov.y = fmaxf(a0.y*rstd*gg.y + be.y, 0.f) + hi.y;
        ov.z = fmaxf(a0.z*rstd*gg.z + be.z, 0.f) + hi.z;
        ov.w = fmaxf(a0.w*rstd*gg.w + be.w, 0.f) + hi.w;
        out[o+0] = ov; outh[o+0] = pack4h(ov);
        gg = g4[c4+1]; be = be4[c4+1]; hi = h[o+1];
        ov.x = fmaxf(a1.x*rstd*gg.x + be.x, 0.f) + hi.x;
        ov.y = fmaxf(a1.y*rstd*gg.y + be.y, 0.f) + hi.y;
        ov.z = fmaxf(a1.z*rstd*gg.z + be.z, 0.f) + hi.z;
        ov.w = fmaxf(a1.w*rstd*gg.w + be.w, 0.f) + hi.w;
        out[o+1] = ov; outh[o+1] = pack4h(ov);
        gg = g4[c4+2]; be = be4[c4+2]; hi = h[o+2];
        ov.x = fmaxf(a2.x*rstd*gg.x + be.x, 0.f) + hi.x;
        ov.y = fmaxf(a2.y*rstd*gg.y + be.y, 0.f) + hi.y;
        ov.z = fmaxf(a2.z*rstd*gg.z + be.z, 0.f) + hi.z;
        ov.w = fmaxf(a2.w*rstd*gg.w + be.w, 0.f) + hi.w;
        out[o+2] = ov; outh[o+2] = pack4h(ov);
        gg = g4[c4+3]; be = be4[c4+3]; hi = h[o+3];
        ov.x = fmaxf(a3.x*rstd*gg.x + be.x, 0.f) + hi.x;
        ov.y = fmaxf(a3.y*rstd*gg.y + be.y, 0.f) + hi.y;
        ov.z = fmaxf(a3.z*rstd*gg.z + be.z, 0.f) + hi.z;
        ov.w = fmaxf(a3.w*rstd*gg.w + be.w, 0.f) + hi.w;
        out[o+3] = ov; outh[o+3] = pack4h(ov);
    }
}

// ---- launch 5: fused projection + scoring (reads fp32 features) ----
__global__ __launch_bounds__(256) void k_proj_score(const float4* __restrict__ h,
                                                    const float* __restrict__ Wp,
                                                    const float* __restrict__ bp,
                                                    const int* __restrict__ users,
                                                    const int* __restrict__ items,
                                                    const float* __restrict__ bu,
                                                    const float* __restrict__ bi,
                                                    const float* __restrict__ mu,
                                                    float* __restrict__ out, int NU) {
    __shared__ __align__(16) float Xs[64][68];
    __shared__ __align__(16) float Ws[64][68];
    int t = threadIdx.x;
    int p0 = blockIdx.x * 64;
    int g = t & 15;

    const float4* W4 = (const float4*)Wp;
    for (int i = t; i < 1024; i += 256)
        *(float4*)&Ws[i >> 4][(i & 15) << 2] = W4[i];

    for (int pass = 0; pass < 4; pass++) {
        int pl = pass * 16 + (t >> 4);
        int u = users[p0 + pl];
        *(float4*)&Xs[pl][g << 2] = h[u * 16 + g];
    }
    __syncthreads();

    int r  = t >> 2;
    int cb = (t & 3) << 4;
    int c4 = cb >> 2;

    float4 u0 = make_float4(0.f,0.f,0.f,0.f), u1 = u0, u2 = u0, u3 = u0;
#pragma unroll
    for (int k = 0; k < 64; k++) {
        float xv = Xs[r][k];
        fma4(u0, xv, *(const float4*)&Ws[k][cb +  0]);
        fma4(u1, xv, *(const float4*)&Ws[k][cb +  4]);
        fma4(u2, xv, *(const float4*)&Ws[k][cb +  8]);
        fma4(u3, xv, *(const float4*)&Ws[k][cb + 12]);
    }
    __syncthreads();

    for (int pass = 0; pass < 4; pass++) {
        int pl = pass * 16 + (t >> 4);
        int it = items[p0 + pl];
        *(float4*)&Xs[pl][g << 2] = h[(NU + it) * 16 + g];
    }
    __syncthreads();

    float4 i0 = make_float4(0.f,0.f,0.f,0.f), i1 = i0, i2 = i0, i3 = i0;
#pragma unroll
    for (int k = 0; k < 64; k++) {
        float xv = Xs[r][k];
        fma4(i0, xv, *(const float4*)&Ws[k][cb +  0]);
        fma4(i1, xv, *(const float4*)&Ws[k][cb +  4]);
        fma4(i2, xv, *(const float4*)&Ws[k][cb +  8]);
        fma4(i3, xv, *(const float4*)&Ws[k][cb + 12]);
    }

    const float4* b4 = (const float4*)bp;
    float4 q;
    float d = 0.f;
    q = b4[c4+0];
    d += (u0.x+q.x)*(i0.x+q.x) + (u0.y+q.y)*(i0.y+q.y)
       + (u0.z+q.z)*(i0.z+q.z) + (u0.w+q.w)*(i0.w+q.w);
    q = b4[c4+1];
    d += (u1.x+q.x)*(i1.x+q.x) + (u1.y+q.y)*(i1.y+q.y)
       + (u1.z+q.z)*(i1.z+q.z) + (u1.w+q.w)*(i1.w+q.w);
    q = b4[c4+2];
    d += (u2.x+q.x)*(i2.x+q.x) + (u2.y+q.y)*(i2.y+q.y)
       + (u2.z+q.z)*(i2.z+q.z) + (u2.w+q.w)*(i2.w+q.w);
    q = b4[c4+3];
    d += (u3.x+q.x)*(i3.x+q.x) + (u3.y+q.y)*(i3.y+q.y)
       + (u3.z+q.z)*(i3.z+q.z) + (u3.w+q.w)*(i3.w+q.w);

    int lane = t & 31;
    unsigned mask4 = 0xFu << (lane & ~3);
    d += __shfl_xor_sync(mask4, d, 1, 4);
    d += __shfl_xor_sync(mask4, d, 2, 4);

    if ((t & 3) == 0) {
        int p = p0 + r;
        float sc = d + bu[users[p]] + bi[items[p]] + mu[0];
        out[p] = fminf(fmaxf(sc, 1.0f), 5.0f);
    }
}

// ---------------- launch ----------------
extern "C" void kernel_launch(void* const* d_in, const int* in_sizes, int n_in,
                              void* d_out, int out_size) {
    const int*    users = (const int*)d_in[0];
    const int*    items = (const int*)d_in[1];
    const int*    eidx  = (const int*)d_in[2];
    const float*  ew    = (const float*)d_in[3];
    const float4* U     = (const float4*)d_in[4];
    const float4* I     = (const float4*)d_in[5];
    const float*  W0    = (const float*)d_in[6];
    const float*  b0    = (const float*)d_in[7];
    const float*  g0    = (const float*)d_in[8];
    const float*  be0   = (const float*)d_in[9];
    const float*  W1    = (const float*)d_in[10];
    const float*  b1    = (const float*)d_in[11];
    const float*  g1    = (const float*)d_in[12];
    const float*  be1   = (const float*)d_in[13];
    const float*  Wp    = (const float*)d_in[14];
    const float*  bp    = (const float*)d_in[15];
    const float*  bu    = (const float*)d_in[16];
    const float*  bi    = (const float*)d_in[17];
    const float*  mu    = (const float*)d_in[18];
    float* out = (float*)d_out;

    int B  = in_sizes[0];
    int E  = in_sizes[3];
    int NU = in_sizes[16];
    int NI = in_sizes[17];
    int N  = NU + NI;
    const int* esrc = eidx;
    const int* edst = eidx + E;

    float4 *p_h, *p_h2, *p_hw;
    uint2  *p_hh, *p_hh2;
    cudaGetSymbolAddress((void**)&p_h,   g_h);
    cudaGetSymbolAddress((void**)&p_h2,  g_h2);
    cudaGetSymbolAddress((void**)&p_hw,  g_hw);
    cudaGetSymbolAddress((void**)&p_hh,  g_hh);
    p_hh2 = (uint2*)p_hw;   // fp16 buffer 2 aliases g_hw scratch

    int nb = (N + 1023) / 1024;   // 147 blocks: single wave

    k_concat <<<(N * 16 + 255) / 256, 256>>>(U, I, NU * 16, N * 16, N);
    k_cntscan<<<nb, 1024>>>(edst, ew, E, N, nb);
    k_fill   <<<2048, 256>>>(esrc, edst, ew, E);
    // launch 3 <-- ncu profiles this
    k_conv   <<<(N + 63) / 64, 256>>>(p_h,  p_hh,  W0, b0, g0, be0, p_h2, p_hh2, N, E);
    k_conv   <<<(N + 63) / 64, 256>>>(p_h2, p_hh2, W1, b1, g1, be1, p_h,  p_hh,  N, E);
    k_proj_score<<<B / 64, 256>>>(p_h, Wp, bp, users, items, bu, bi, mu, out, NU);
}

// round 16
// speedup vs baseline: 2.5053x; 1.0365x over previous
#include <cuda_runtime.h>
#include <cuda_fp16.h>
#include <math.h>

#define NMAX 150016
#define EMAX 3200064

// ---------------- static device scratch ----------------
__device__ float  g_dinv[NMAX];
__device__ unsigned long long g_cd[NMAX];   // count<<40 | sum(w * 2^24); re-zeroed each run
__device__ int    g_rank[EMAX];             // per-edge rank within dst bucket
__device__ int    g_rs[NMAX + 2];
__device__ int    g_bsum[1024];
__device__ int    g_bsumP[1024];
__device__ int    g_bar;                    // reset to 0 by block 0 at end of cntscan
__device__ __align__(16) int2 g_csr[EMAX];  // {src, dinv[src]*ew bits}
__device__ float4 g_hw[NMAX * 16];          // scratch (aliased as fp16 buf2)
__device__ float4 g_h [NMAX * 16];          // fp32 features ping
__device__ float4 g_h2[NMAX * 16];          // fp32 features pong
__device__ uint2  g_hh[NMAX * 16];          // fp16 gather copy

__device__ __forceinline__ void fma4(float4& a, float s, const float4& w) {
    a.x += s * w.x; a.y += s * w.y; a.z += s * w.z; a.w += s * w.w;
}
__device__ __forceinline__ uint2 pack4h(const float4& v) {
    __half2 lo = __float22half2_rn(make_float2(v.x, v.y));
    __half2 hi = __float22half2_rn(make_float2(v.z, v.w));
    uint2 r;
    r.x = *(const unsigned*)&lo;
    r.y = *(const unsigned*)&hi;
    return r;
}
__device__ __forceinline__ void acc_h(float4& acc, float ww, const uint2& pv) {
    float2 f0 = __half22float2(*(const __half2*)&pv.x);
    float2 f1 = __half22float2(*(const __half2*)&pv.y);
    acc.x += ww * f0.x; acc.y += ww * f0.y;
    acc.z += ww * f1.x; acc.w += ww * f1.y;
}
__device__ __forceinline__ unsigned smem_u32(const void* p) {
    return (unsigned)__cvta_generic_to_shared(p);
}

// ---------------- software grid barrier (single-wave persistent kernel) -------
__device__ __forceinline__ void gsync(int target) {
    __syncthreads();
    __threadfence();
    if (threadIdx.x == 0) {
        atomicAdd(&g_bar, 1);
        while (atomicAdd(&g_bar, 0) < target) { }
        __threadfence();
    }
    __syncthreads();
}

// ---- launch 0: concat + count/rank (packed 64-bit atomic) + scan + dinv ----
// g_cd must be zero on entry (zero-init at load; re-zeroed in phase 2 each run).
// g_bar must be zero on entry (zero-init; reset by block 0 at end).
__global__ __launch_bounds__(1024) void k_cntscan(const float4* __restrict__ U,
                                                  const float4* __restrict__ I,
                                                  const int* __restrict__ dst,
                                                  const float* __restrict__ ew,
                                                  int nu16, int tot16,
                                                  int E, int N, int nb) {
    __shared__ int sm[1024];
    int t = threadIdx.x, b = blockIdx.x;
    int gstride = nb * 1024;
    int gid = b * 1024 + t;

    // phase 1a: concat x=[U;I] into fp32 + fp16 buffers
    for (int i = gid; i < tot16; i += gstride) {
        float4 v = (i < nu16) ? U[i] : I[i - nu16];
        g_h[i]  = v;
        g_hh[i] = pack4h(v);
    }
    // phase 1b: per-dst count + weighted degree + per-edge rank (one atomic)
    for (int e = gid; e < E; e += gstride) {
        int d = dst[e];
        unsigned long long pk = (1ULL << 40)
            | (unsigned long long)__float2uint_rn(ew[e] * 16777216.0f);
        unsigned long long old = atomicAdd(&g_cd[d], pk);
        g_rank[e] = (int)(old >> 40);
    }
    gsync(nb);

    // phase 2: block-local exclusive scan of counts + dinv + re-zero g_cd
    int i = gid;
    unsigned long long cd = (i < N) ? g_cd[i] : 0ULL;
    int x = (int)(cd >> 40);
    sm[t] = x;
    __syncthreads();
    for (int o = 1; o < 1024; o <<= 1) {
        int v = (t >= o) ? sm[t - o] : 0;
        __syncthreads();
        sm[t] += v;
        __syncthreads();
    }
    if (i < N) {
        g_rs[i] = sm[t] - x;
        float deg = 1.0f + (float)(cd & 0xFFFFFFFFFFULL) * (1.0f / 16777216.0f);
        g_dinv[i] = rsqrtf(deg);
        g_cd[i] = 0ULL;                    // clean for next graph replay
    }
    if (t == 1023) g_bsum[b] = sm[1023];
    gsync(2 * nb);

    // phase 3: block 0 scans per-block sums, then resets the barrier
    if (b == 0) {
        int y = (t < nb) ? g_bsum[t] : 0;
        sm[t] = y;
        __syncthreads();
        for (int o = 1; o < 1024; o <<= 1) {
            int v = (t >= o) ? sm[t - o] : 0;
            __syncthreads();
            sm[t] += v;
            __syncthreads();
        }
        if (t < nb) g_bsumP[t] = sm[t] - y;
        __syncthreads();
        if (t == 0) g_bar = 0;             // clean for next graph replay
    }
}

// ---------------- launch 1: CSR fill (NO atomics; uses precomputed rank) -------
__global__ void k_fill(const int* __restrict__ src, const int* __restrict__ dst,
                       const float* __restrict__ ew, int E) {
    for (int e = blockIdx.x * blockDim.x + threadIdx.x; e < E; e += gridDim.x * blockDim.x) {
        int d = dst[e];
        int s = src[e];
        int p = g_rs[d] + g_bsumP[d >> 10] + g_rank[e];
        g_csr[p] = make_int2(s, __float_as_int(g_dinv[s] * ew[e]));
    }
}

// ---- launch 2/3: fused conv: a = S h (fp16 gather); y = a@W via HMMA; LN; ReLU; +h --
__global__ __launch_bounds__(256, 4) void k_conv(const float4* __restrict__ h,
                                                 const uint2*  __restrict__ hh,
                                                 const float* __restrict__ W,
                                                 const float* __restrict__ bconv,
                                                 const float* __restrict__ gam,
                                                 const float* __restrict__ bet,
                                                 float4* __restrict__ out,
                                                 uint2*  __restrict__ outh,
                                                 int N, int E) {
    __shared__ __align__(16) __half Xh[64][72];   // aggregated tile, fp16
    __shared__ __align__(16) __half Wh[64][72];   // W, fp16
    __shared__ __align__(16) float  Ys[64][68];   // mma result, fp32
    int t = threadIdx.x;
    int row0 = blockIdx.x * 64;

    // W fp32 -> fp16 smem
    const float4* W4 = (const float4*)W;
    for (int i = t; i < 1024; i += 256) {
        int k = i >> 4, c4 = i & 15;
        *(uint2*)&Wh[k][c4 << 2] = pack4h(W4[i]);
    }

    // gather phase: 16-lane group per node, fp16 gather, fp32 acc
    int g = t & 15;
    for (int pass = 0; pass < 4; pass++) {
        int nl = pass * 16 + (t >> 4);
        int node = row0 + nl;
        float4 acc = make_float4(0.f, 0.f, 0.f, 0.f);
        float dvd = 0.f;
        float4 hs = acc;
        if (node < N) {
            dvd = g_dinv[node];
            hs  = h[node * 16 + g];
            int e0 = g_rs[node] + g_bsumP[node >> 10];
            int e1 = (node + 1 < N) ? (g_rs[node + 1] + g_bsumP[(node + 1) >> 10]) : E;
            int e  = e0;
            if (e < e1 && (e & 1)) {
                int2 ce = g_csr[e];
                acc_h(acc, __int_as_float(ce.y), hh[ce.x * 16 + g]);
                e++;
            }
            int npairs = (e1 - e) >> 1;
            const int4* c4p = (const int4*)(g_csr + e);
            int i = 0;
            for (; i + 4 <= npairs; i += 4) {
                int4 ca = c4p[i];
                int4 cb = c4p[i + 1];
                int4 cc = c4p[i + 2];
                int4 cd = c4p[i + 3];
                uint2 p0 = hh[ca.x * 16 + g];
                uint2 p1 = hh[ca.z * 16 + g];
                uint2 p2 = hh[cb.x * 16 + g];
                uint2 p3 = hh[cb.z * 16 + g];
                uint2 p4 = hh[cc.x * 16 + g];
                uint2 p5 = hh[cc.z * 16 + g];
                uint2 p6 = hh[cd.x * 16 + g];
                uint2 p7 = hh[cd.z * 16 + g];
                acc_h(acc, __int_as_float(ca.y), p0);
                acc_h(acc, __int_as_float(ca.w), p1);
                acc_h(acc, __int_as_float(cb.y), p2);
                acc_h(acc, __int_as_float(cb.w), p3);
                acc_h(acc, __int_as_float(cc.y), p4);
                acc_h(acc, __int_as_float(cc.w), p5);
                acc_h(acc, __int_as_float(cd.y), p6);
                acc_h(acc, __int_as_float(cd.w), p7);
            }
            for (; i < npairs; i++) {
                int4 ca = c4p[i];
                uint2 p0 = hh[ca.x * 16 + g];
                uint2 p1 = hh[ca.z * 16 + g];
                acc_h(acc, __int_as_float(ca.y), p0);
                acc_h(acc, __int_as_float(ca.w), p1);
            }
            if ((e1 - e) & 1) {
                int2 ce = g_csr[e1 - 1];
                acc_h(acc, __int_as_float(ce.y), hh[ce.x * 16 + g]);
            }
        }
        float4 a;
        a.x = dvd * (acc.x + dvd * hs.x);
        a.y = dvd * (acc.y + dvd * hs.y);
        a.z = dvd * (acc.z + dvd * hs.z);
        a.w = dvd * (acc.w + dvd * hs.w);
        *(uint2*)&Xh[nl][g << 2] = pack4h(a);
    }
    __syncthreads();

    // ---- HMMA GEMM: warps 0-3, each m16 x n64, k=64 ----
    int w = t >> 5, lane = t & 31;
    if (w < 4) {
        float acc[8][4];
#pragma unroll
        for (int nt = 0; nt < 8; nt++) {
            acc[nt][0] = 0.f; acc[nt][1] = 0.f; acc[nt][2] = 0.f; acc[nt][3] = 0.f;
        }
#pragma unroll
        for (int ks = 0; ks < 4; ks++) {
            unsigned a0, a1, a2, a3;
            unsigned aaddr = smem_u32(&Xh[w * 16 + (lane & 15)][ks * 16 + ((lane >> 4) << 3)]);
            asm volatile("ldmatrix.sync.aligned.m8n8.x4.shared.b16 {%0,%1,%2,%3}, [%4];"
                         : "=r"(a0), "=r"(a1), "=r"(a2), "=r"(a3) : "r"(aaddr));
#pragma unroll
            for (int nt = 0; nt < 8; nt += 2) {
                unsigned b0, b1, b2, b3;
                unsigned baddr = smem_u32(&Wh[ks * 16 + (lane & 15)][nt * 8 + ((lane >> 4) << 3)]);
                asm volatile("ldmatrix.sync.aligned.m8n8.x4.trans.shared.b16 {%0,%1,%2,%3}, [%4];"
                             : "=r"(b0), "=r"(b1), "=r"(b2), "=r"(b3) : "r"(baddr));
                asm volatile("mma.sync.aligned.m16n8k16.row.col.f32.f16.f16.f32 "
                             "{%0,%1,%2,%3}, {%4,%5,%6,%7}, {%8,%9}, {%0,%1,%2,%3};"
                             : "+f"(acc[nt][0]), "+f"(acc[nt][1]), "+f"(acc[nt][2]), "+f"(acc[nt][3])
                             : "r"(a0), "r"(a1), "r"(a2), "r"(a3), "r"(b0), "r"(b1));
                asm volatile("mma.sync.aligned.m16n8k16.row.col.f32.f16.f16.f32 "
                             "{%0,%1,%2,%3}, {%4,%5,%6,%7}, {%8,%9}, {%0,%1,%2,%3};"
                             : "+f"(acc[nt+1][0]), "+f"(acc[nt+1][1]), "+f"(acc[nt+1][2]), "+f"(acc[nt+1][3])
                             : "r"(a0), "r"(a1), "r"(a2), "r"(a3), "r"(b2), "r"(b3));
            }
        }
        int r0 = w * 16 + (lane >> 2);
        int c0 = (lane & 3) << 1;
#pragma unroll
        for (int nt = 0; nt < 8; nt++) {
            *(float2*)&Ys[r0    ][nt * 8 + c0] = make_float2(acc[nt][0], acc[nt][1]);
            *(float2*)&Ys[r0 + 8][nt * 8 + c0] = make_float2(acc[nt][2], acc[nt][3]);
        }
    }
    __syncthreads();

    // ---- epilogue: bias + LN + ReLU + residual ----
    int r  = t >> 2;
    int cb = (t & 3) << 4;
    int c4 = cb >> 2;
    float4 a0 = *(const float4*)&Ys[r][cb +  0];
    float4 a1 = *(const float4*)&Ys[r][cb +  4];
    float4 a2 = *(const float4*)&Ys[r][cb +  8];
    float4 a3 = *(const float4*)&Ys[r][cb + 12];

    const float4* b4 = (const float4*)bconv;
    float4 q;
    q = b4[c4+0]; a0.x+=q.x; a0.y+=q.y; a0.z+=q.z; a0.w+=q.w;
    q = b4[c4+1]; a1.x+=q.x; a1.y+=q.y; a1.z+=q.z; a1.w+=q.w;
    q = b4[c4+2]; a2.x+=q.x; a2.y+=q.y; a2.z+=q.z; a2.w+=q.w;
    q = b4[c4+3]; a3.x+=q.x; a3.y+=q.y; a3.z+=q.z; a3.w+=q.w;

    int lane2 = t & 31;
    unsigned mask4 = 0xFu << (lane2 & ~3);
    float s = (a0.x+a0.y+a0.z+a0.w) + (a1.x+a1.y+a1.z+a1.w)
            + (a2.x+a2.y+a2.z+a2.w) + (a3.x+a3.y+a3.z+a3.w);
    s += __shfl_xor_sync(mask4, s, 1, 4);
    s += __shfl_xor_sync(mask4, s, 2, 4);
    float m = s * (1.0f / 64.0f);
    a0.x-=m; a0.y-=m; a0.z-=m; a0.w-=m;
    a1.x-=m; a1.y-=m; a1.z-=m; a1.w-=m;
    a2.x-=m; a2.y-=m; a2.z-=m; a2.w-=m;
    a3.x-=m; a3.y-=m; a3.z-=m; a3.w-=m;
    float vs = (a0.x*a0.x+a0.y*a0.y+a0.z*a0.z+a0.w*a0.w)
             + (a1.x*a1.x+a1.y*a1.y+a1.z*a1.z+a1.w*a1.w)
             + (a2.x*a2.x+a2.y*a2.y+a2.z*a2.z+a2.w*a2.w)
             + (a3.x*a3.x+a3.y*a3.y+a3.z*a3.z+a3.w*a3.w);
    vs += __shfl_xor_sync(mask4, vs, 1, 4);
    vs += __shfl_xor_sync(mask4, vs, 2, 4);
    float rstd = rsqrtf(vs * (1.0f / 64.0f) + 1e-5f);

    const float4* g4  = (const float4*)gam;
    const float4* be4 = (const float4*)bet;
    int grow = row0 + r;
    if (grow < N) {
        int o = grow * 16 + c4;
        float4 gg, be, hi, ov;
        gg = g4[c4+0]; be = be4[c4+0]; hi = h[o+0];
        ov.x = fmaxf(a0.x*rstd*gg.x + be.x, 0.f) + hi.x;
        ov.y = fmaxf(a0.y*rstd*gg.y + be.y, 0.f) + hi.y;
        ov.z = fmaxf(a0.z*rstd*gg.z + be.z, 0.f) + hi.z;
        ov.w = fmaxf(a0.w*rstd*gg.w + be.w, 0.f) + hi.w;
        out[o+0] = ov; outh[o+0] = pack4h(ov);
        gg = g4[c4+1]; be = be4[c4+1]; hi = h[o+1];
        ov.x = fmaxf(a1.x*rstd*gg.x + be.x, 0.f) + hi.x;
        ov.y = fmaxf(a1.y*rstd*gg.y + be.y, 0.f) + hi.y;
        ov.z = fmaxf(a1.z*rstd*gg.z + be.z, 0.f) + hi.z;
        ov.w = fmaxf(a1.w*rstd*gg.w + be.w, 0.f) + hi.w;
        out[o+1] = ov; outh[o+1] = pack4h(ov);
        gg = g4[c4+2]; be = be4[c4+2]; hi = h[o+2];
        ov.x = fmaxf(a2.x*rstd*gg.x + be.x, 0.f) + hi.x;
        ov.y = fmaxf(a2.y*rstd*gg.y + be.y, 0.f) + hi.y;
        ov.z = fmaxf(a2.z*rstd*gg.z + be.z, 0.f) + hi.z;
        ov.w = fmaxf(a2.w*rstd*gg.w + be.w, 0.f) + hi.w;
        out[o+2] = ov; outh[o+2] = pack4h(ov);
        gg = g4[c4+3]; be = be4[c4+3]; hi = h[o+3];
        ov.x = fmaxf(a3.x*rstd*gg.x + be.x, 0.f) + hi.x;
        ov.y = fmaxf(a3.y*rstd*gg.y + be.y, 0.f) + hi.y;
        ov.z = fmaxf(a3.z*rstd*gg.z + be.z, 0.f) + hi.z;
        ov.w = fmaxf(a3.w*rstd*gg.w + be.w, 0.f) + hi.w;
        out[o+3] = ov; outh[o+3] = pack4h(ov);
    }
}

// ---- launch 4: fused projection + scoring (reads fp32 features) ----
__global__ __launch_bounds__(256) void k_proj_score(const float4* __restrict__ h,
                                                    const float* __restrict__ Wp,
                                                    const float* __restrict__ bp,
                                                    const int* __restrict__ users,
                                                    const int* __restrict__ items,
                                                    const float* __restrict__ bu,
                                                    const float* __restrict__ bi,
                                                    const float* __restrict__ mu,
                                                    float* __restrict__ out, int NU) {
    __shared__ __align__(16) float Xs[64][68];
    __shared__ __align__(16) float Ws[64][68];
    int t = threadIdx.x;
    int p0 = blockIdx.x * 64;
    int g = t & 15;

    const float4* W4 = (const float4*)Wp;
    for (int i = t; i < 1024; i += 256)
        *(float4*)&Ws[i >> 4][(i & 15) << 2] = W4[i];

    for (int pass = 0; pass < 4; pass++) {
        int pl = pass * 16 + (t >> 4);
        int u = users[p0 + pl];
        *(float4*)&Xs[pl][g << 2] = h[u * 16 + g];
    }
    __syncthreads();

    int r  = t >> 2;
    int cb = (t & 3) << 4;
    int c4 = cb >> 2;

    float4 u0 = make_float4(0.f,0.f,0.f,0.f), u1 = u0, u2 = u0, u3 = u0;
#pragma unroll
    for (int k = 0; k < 64; k++) {
        float xv = Xs[r][k];
        fma4(u0, xv, *(const float4*)&Ws[k][cb +  0]);
        fma4(u1, xv, *(const float4*)&Ws[k][cb +  4]);
        fma4(u2, xv, *(const float4*)&Ws[k][cb +  8]);
        fma4(u3, xv, *(const float4*)&Ws[k][cb + 12]);
    }
    __syncthreads();

    for (int pass = 0; pass < 4; pass++) {
        int pl = pass * 16 + (t >> 4);
        int it = items[p0 + pl];
        *(float4*)&Xs[pl][g << 2] = h[(NU + it) * 16 + g];
    }
    __syncthreads();

    float4 i0 = make_float4(0.f,0.f,0.f,0.f), i1 = i0, i2 = i0, i3 = i0;
#pragma unroll
    for (int k = 0; k < 64; k++) {
        float xv = Xs[r][k];
        fma4(i0, xv, *(const float4*)&Ws[k][cb +  0]);
        fma4(i1, xv, *(const float4*)&Ws[k][cb +  4]);
        fma4(i2, xv, *(const float4*)&Ws[k][cb +  8]);
        fma4(i3, xv, *(const float4*)&Ws[k][cb + 12]);
    }

    const float4* b4 = (const float4*)bp;
    float4 q;
    float d = 0.f;
    q = b4[c4+0];
    d += (u0.x+q.x)*(i0.x+q.x) + (u0.y+q.y)*(i0.y+q.y)
       + (u0.z+q.z)*(i0.z+q.z) + (u0.w+q.w)*(i0.w+q.w);
    q = b4[c4+1];
    d += (u1.x+q.x)*(i1.x+q.x) + (u1.y+q.y)*(i1.y+q.y)
       + (u1.z+q.z)*(i1.z+q.z) + (u1.w+q.w)*(i1.w+q.w);
    q = b4[c4+2];
    d += (u2.x+q.x)*(i2.x+q.x) + (u2.y+q.y)*(i2.y+q.y)
       + (u2.z+q.z)*(i2.z+q.z) + (u2.w+q.w)*(i2.w+q.w);
    q = b4[c4+3];
    d += (u3.x+q.x)*(i3.x+q.x) + (u3.y+q.y)*(i3.y+q.y)
       + (u3.z+q.z)*(i3.z+q.z) + (u3.w+q.w)*(i3.w+q.w);

    int lane = t & 31;
    unsigned mask4 = 0xFu << (lane & ~3);
    d += __shfl_xor_sync(mask4, d, 1, 4);
    d += __shfl_xor_sync(mask4, d, 2, 4);

    if ((t & 3) == 0) {
        int p = p0 + r;
        float sc = d + bu[users[p]] + bi[items[p]] + mu[0];
        out[p] = fminf(fmaxf(sc, 1.0f), 5.0f);
    }
}

// ---------------- launch ----------------
extern "C" void kernel_launch(void* const* d_in, const int* in_sizes, int n_in,
                              void* d_out, int out_size) {
    const int*    users = (const int*)d_in[0];
    const int*    items = (const int*)d_in[1];
    const int*    eidx  = (const int*)d_in[2];
    const float*  ew    = (const float*)d_in[3];
    const float4* U     = (const float4*)d_in[4];
    const float4* I     = (const float4*)d_in[5];
    const float*  W0    = (const float*)d_in[6];
    const float*  b0    = (const float*)d_in[7];
    const float*  g0    = (const float*)d_in[8];
    const float*  be0   = (const float*)d_in[9];
    const float*  W1    = (const float*)d_in[10];
    const float*  b1    = (const float*)d_in[11];
    const float*  g1    = (const float*)d_in[12];
    const float*  be1   = (const float*)d_in[13];
    const float*  Wp    = (const float*)d_in[14];
    const float*  bp    = (const float*)d_in[15];
    const float*  bu    = (const float*)d_in[16];
    const float*  bi    = (const float*)d_in[17];
    const float*  mu    = (const float*)d_in[18];
    float* out = (float*)d_out;

    int B  = in_sizes[0];
    int E  = in_sizes[3];
    int NU = in_sizes[16];
    int NI = in_sizes[17];
    int N  = NU + NI;
    const int* esrc = eidx;
    const int* edst = eidx + E;

    float4 *p_h, *p_h2, *p_hw;
    uint2  *p_hh, *p_hh2;
    cudaGetSymbolAddress((void**)&p_h,   g_h);
    cudaGetSymbolAddress((void**)&p_h2,  g_h2);
    cudaGetSymbolAddress((void**)&p_hw,  g_hw);
    cudaGetSymbolAddress((void**)&p_hh,  g_hh);
    p_hh2 = (uint2*)p_hw;   // fp16 buffer 2 aliases g_hw scratch

    int nb = (N + 1023) / 1024;   // 147 blocks: single wave

    // launch 0: concat + count/rank + scan (persistent, self-cleaning state)
    k_cntscan<<<nb, 1024>>>(U, I, edst, ew, NU * 16, N * 16, E, N, nb);
    // launch 1: atomic-free CSR fill
    k_fill   <<<2048, 256>>>(esrc, edst, ew, E);
    // launch 2/3: conv layers  (ncu profiles launch 3 = conv layer 2)
    k_conv   <<<(N + 63) / 64, 256>>>(p_h,  p_hh,  W0, b0, g0, be0, p_h2, p_hh2, N, E);
    k_conv   <<<(N + 63) / 64, 256>>>(p_h2, p_hh2, W1, b1, g1, be1, p_h,  p_hh,  N, E);
    // launch 4: fused projection + scoring
    k_proj_score<<<B / 64, 256>>>(p_h, Wp, bp, users, items, bu, bi, mu, out, NU);
}